// round 1
// baseline (speedup 1.0000x reference)
#include <cuda_runtime.h>
#include <math.h>

// Problem constants
#define BB 2
#define SS 1024
#define DD 2048
#define FF 8192
#define EE 4
#define KK 2
#define NT (BB*SS)   // 2048 tokens

// ---------------- device scratch (no allocations allowed) ----------------
__device__ int   g_cnt[EE];
__device__ int   g_tok[EE][NT];
__device__ float g_gate[EE][NT];
__device__ float g_H[(size_t)NT * FF];   // 64 MB intermediate (reused per expert; stream-serialized)

// ---------------- init: zero output + counters ----------------
__global__ void init_kernel(float* __restrict__ out, int n) {
    int i = blockIdx.x * blockDim.x + threadIdx.x;
    if (i < n) out[i] = 0.0f;
    if (i < EE) g_cnt[i] = 0;
}

// ---------------- router: logits -> softmax -> top2 -> expert lists ----------------
// One warp per token.
__global__ void router_kernel(const float* __restrict__ x, const float* __restrict__ Wr) {
    int gwarp = (blockIdx.x * blockDim.x + threadIdx.x) >> 5;
    int lane  = threadIdx.x & 31;
    if (gwarp >= NT) return;

    const float* xr = x + (size_t)gwarp * DD;
    float a0 = 0.f, a1 = 0.f, a2 = 0.f, a3 = 0.f;
    for (int d = lane; d < DD; d += 32) {
        float xv = xr[d];
        float4 w = *(const float4*)(Wr + (size_t)d * 4);   // E=4 contiguous
        a0 += xv * w.x; a1 += xv * w.y; a2 += xv * w.z; a3 += xv * w.w;
    }
    #pragma unroll
    for (int off = 16; off; off >>= 1) {
        a0 += __shfl_down_sync(0xffffffffu, a0, off);
        a1 += __shfl_down_sync(0xffffffffu, a1, off);
        a2 += __shfl_down_sync(0xffffffffu, a2, off);
        a3 += __shfl_down_sync(0xffffffffu, a3, off);
    }
    if (lane == 0) {
        float l[4] = {a0, a1, a2, a3};
        float m = fmaxf(fmaxf(l[0], l[1]), fmaxf(l[2], l[3]));
        float p[4], s = 0.f;
        #pragma unroll
        for (int e = 0; e < 4; e++) { p[e] = expf(l[e] - m); s += p[e]; }
        // top-1 (strict >, ascending scan -> lowest index wins ties, matching lax.top_k)
        int i0 = 0; float b0 = p[0];
        #pragma unroll
        for (int e = 1; e < 4; e++) if (p[e] > b0) { b0 = p[e]; i0 = e; }
        int i1 = -1; float b1 = -1.f;
        #pragma unroll
        for (int e = 0; e < 4; e++) if (e != i0 && p[e] > b1) { b1 = p[e]; i1 = e; }

        float inv = 1.f / s;
        int pos0 = atomicAdd(&g_cnt[i0], 1);
        g_tok[i0][pos0]  = gwarp;
        g_gate[i0][pos0] = b0 * inv;
        int pos1 = atomicAdd(&g_cnt[i1], 1);
        g_tok[i1][pos1]  = gwarp;
        g_gate[i1][pos1] = b1 * inv;
    }
}

// ---------------- GEMM1: fused gate+up + SiLU*mul epilogue ----------------
// C[row, f] over rows of expert e's token list; tiles: BM=128, BN=64, BK=16; 256 threads, 8x4/thread (x2 accum sets)
__global__ __launch_bounds__(256) void gemm_gateup_kernel(
    const float* __restrict__ x, const float* __restrict__ Wg,
    const float* __restrict__ Wu, int e)
{
    const int ne = g_cnt[e];
    const int rb = blockIdx.y;
    if (rb * 128 >= ne) return;
    const int nb = blockIdx.x;           // n0 = nb*64 within F

    __shared__ float As[16][132];        // padded (132%4==0 keeps float4 alignment)
    __shared__ float Bgs[16][64];
    __shared__ float Bus[16][64];

    const int tid = threadIdx.x;
    const int tx = tid & 15;
    const int ty = tid >> 4;

    // A-tile loader mapping: two float4/thread
    const int r0   = tid >> 2;           // 0..63
    const int c4   = tid & 3;            // which float4 within the 16-wide k slab
    const int grow0 = rb * 128 + r0;
    const int grow1 = grow0 + 64;
    const int* toks = g_tok[e];
    const float* a0 = x + (size_t)((grow0 < ne) ? toks[grow0] : 0) * DD;
    const float* a1 = x + (size_t)((grow1 < ne) ? toks[grow1] : 0) * DD;

    // B-tile loader mapping: one float4/thread per matrix
    const int bk = tid >> 4;             // 0..15
    const int bc = (tid & 15) * 4;
    const float* wg = Wg + (size_t)e * DD * FF + (size_t)bk * FF + (size_t)nb * 64 + bc;
    const float* wu = Wu + (size_t)e * DD * FF + (size_t)bk * FF + (size_t)nb * 64 + bc;

    float accg[8][4], accu[8][4];
    #pragma unroll
    for (int i = 0; i < 8; i++)
        #pragma unroll
        for (int j = 0; j < 4; j++) { accg[i][j] = 0.f; accu[i][j] = 0.f; }

    #pragma unroll 1
    for (int k0 = 0; k0 < DD; k0 += 16) {
        float4 av0 = *(const float4*)(a0 + k0 + c4 * 4);
        float4 av1 = *(const float4*)(a1 + k0 + c4 * 4);
        float4 bgv = *(const float4*)(wg + (size_t)k0 * FF);
        float4 buv = *(const float4*)(wu + (size_t)k0 * FF);

        __syncthreads();
        As[c4*4+0][r0] = av0.x; As[c4*4+1][r0] = av0.y; As[c4*4+2][r0] = av0.z; As[c4*4+3][r0] = av0.w;
        As[c4*4+0][r0+64] = av1.x; As[c4*4+1][r0+64] = av1.y; As[c4*4+2][r0+64] = av1.z; As[c4*4+3][r0+64] = av1.w;
        *(float4*)&Bgs[bk][bc] = bgv;
        *(float4*)&Bus[bk][bc] = buv;
        __syncthreads();

        #pragma unroll
        for (int kk = 0; kk < 16; kk++) {
            float4 aA = *(const float4*)&As[kk][ty*8];
            float4 aB = *(const float4*)&As[kk][ty*8+4];
            float a[8] = {aA.x,aA.y,aA.z,aA.w,aB.x,aB.y,aB.z,aB.w};
            float4 bg = *(const float4*)&Bgs[kk][tx*4];
            float4 bu = *(const float4*)&Bus[kk][tx*4];
            float bga[4] = {bg.x,bg.y,bg.z,bg.w};
            float bua[4] = {bu.x,bu.y,bu.z,bu.w};
            #pragma unroll
            for (int i = 0; i < 8; i++)
                #pragma unroll
                for (int j = 0; j < 4; j++) {
                    accg[i][j] += a[i] * bga[j];
                    accu[i][j] += a[i] * bua[j];
                }
        }
    }

    // epilogue: H = silu(g) * u
    #pragma unroll
    for (int i = 0; i < 8; i++) {
        int grow = rb * 128 + ty * 8 + i;
        if (grow < ne) {
            float* hrow = g_H + (size_t)grow * FF + (size_t)nb * 64 + tx * 4;
            #pragma unroll
            for (int j = 0; j < 4; j++) {
                float g = accg[i][j];
                float h = (g / (1.f + expf(-g))) * accu[i][j];
                hrow[j] = h;
            }
        }
    }
}

// ---------------- GEMM2: down-proj + gated scatter-add epilogue ----------------
__global__ __launch_bounds__(256) void gemm_down_kernel(
    const float* __restrict__ Wd, float* __restrict__ out, int e)
{
    const int ne = g_cnt[e];
    const int rb = blockIdx.y;
    if (rb * 128 >= ne) return;
    const int nb = blockIdx.x;           // n0 = nb*64 within D

    __shared__ float As[16][132];
    __shared__ float Bs[16][64];

    const int tid = threadIdx.x;
    const int tx = tid & 15;
    const int ty = tid >> 4;

    const int r0 = tid >> 2;
    const int c4 = tid & 3;
    const float* a0 = g_H + (size_t)(rb * 128 + r0) * FF;       // rows always < NT, in-bounds
    const float* a1 = a0 + (size_t)64 * FF;

    const int bk = tid >> 4;
    const int bc = (tid & 15) * 4;
    const float* wd = Wd + (size_t)e * FF * DD + (size_t)bk * DD + (size_t)nb * 64 + bc;

    float acc[8][4];
    #pragma unroll
    for (int i = 0; i < 8; i++)
        #pragma unroll
        for (int j = 0; j < 4; j++) acc[i][j] = 0.f;

    #pragma unroll 1
    for (int k0 = 0; k0 < FF; k0 += 16) {
        float4 av0 = *(const float4*)(a0 + k0 + c4 * 4);
        float4 av1 = *(const float4*)(a1 + k0 + c4 * 4);
        float4 bv  = *(const float4*)(wd + (size_t)k0 * DD);

        __syncthreads();
        As[c4*4+0][r0] = av0.x; As[c4*4+1][r0] = av0.y; As[c4*4+2][r0] = av0.z; As[c4*4+3][r0] = av0.w;
        As[c4*4+0][r0+64] = av1.x; As[c4*4+1][r0+64] = av1.y; As[c4*4+2][r0+64] = av1.z; As[c4*4+3][r0+64] = av1.w;
        *(float4*)&Bs[bk][bc] = bv;
        __syncthreads();

        #pragma unroll
        for (int kk = 0; kk < 16; kk++) {
            float4 aA = *(const float4*)&As[kk][ty*8];
            float4 aB = *(const float4*)&As[kk][ty*8+4];
            float a[8] = {aA.x,aA.y,aA.z,aA.w,aB.x,aB.y,aB.z,aB.w};
            float4 b = *(const float4*)&Bs[kk][tx*4];
            float ba[4] = {b.x,b.y,b.z,b.w};
            #pragma unroll
            for (int i = 0; i < 8; i++)
                #pragma unroll
                for (int j = 0; j < 4; j++)
                    acc[i][j] += a[i] * ba[j];
        }
    }

    const int* toks = g_tok[e];
    const float* gts = g_gate[e];
    #pragma unroll
    for (int i = 0; i < 8; i++) {
        int grow = rb * 128 + ty * 8 + i;
        if (grow < ne) {
            int   tok = toks[grow];
            float gv  = gts[grow];
            float* orow = out + (size_t)tok * DD + (size_t)nb * 64 + tx * 4;
            #pragma unroll
            for (int j = 0; j < 4; j++)
                atomicAdd(&orow[j], acc[i][j] * gv);
        }
    }
}

// ---------------- launch ----------------
extern "C" void kernel_launch(void* const* d_in, const int* in_sizes, int n_in,
                              void* d_out, int out_size) {
    const float* x  = (const float*)d_in[0];
    const float* Wr = (const float*)d_in[1];
    const float* Wg = (const float*)d_in[2];
    const float* Wu = (const float*)d_in[3];
    const float* Wd = (const float*)d_in[4];
    float* out = (float*)d_out;

    const int n_out = NT * DD;
    init_kernel<<<(n_out + 255) / 256, 256>>>(out, n_out);

    // router: 1 warp/token -> 2048 warps -> 512 blocks of 128 threads
    router_kernel<<<(NT * 32 + 127) / 128, 128>>>(x, Wr);

    for (int e = 0; e < EE; e++) {
        gemm_gateup_kernel<<<dim3(FF / 64, 16), 256>>>(x, Wg, Wu, e);
        gemm_down_kernel<<<dim3(DD / 64, 16), 256>>>(Wd, out, e);
    }
}

// round 4
// speedup vs baseline: 1.3455x; 1.3455x over previous
#include <cuda_runtime.h>
#include <cuda_bf16.h>
#include <mma.h>
#include <math.h>

using namespace nvcuda;

// Problem constants
#define BB 2
#define SS 1024
#define DD 2048
#define FF 8192
#define EE 4
#define KK 2
#define NT (BB*SS)   // 2048 tokens

// ---------------- device scratch (no allocations allowed) ----------------
__device__ int   g_cnt[EE];
__device__ int   g_tok[EE][NT];
__device__ float g_gate[EE][NT];
__device__ float g_H[(size_t)NT * FF];   // 64 MB intermediate (reused per expert; stream-serialized)

// ---------------- init: zero output + counters ----------------
__global__ void init_kernel(float* __restrict__ out, int n) {
    int i = blockIdx.x * blockDim.x + threadIdx.x;
    if (i < n) out[i] = 0.0f;
    if (i < EE) g_cnt[i] = 0;
}

// ---------------- router: logits -> softmax -> top2 -> expert lists ----------------
__global__ void router_kernel(const float* __restrict__ x, const float* __restrict__ Wr) {
    int gwarp = (blockIdx.x * blockDim.x + threadIdx.x) >> 5;
    int lane  = threadIdx.x & 31;
    if (gwarp >= NT) return;

    const float* xr = x + (size_t)gwarp * DD;
    float a0 = 0.f, a1 = 0.f, a2 = 0.f, a3 = 0.f;
    for (int d = lane; d < DD; d += 32) {
        float xv = xr[d];
        float4 w = *(const float4*)(Wr + (size_t)d * 4);
        a0 += xv * w.x; a1 += xv * w.y; a2 += xv * w.z; a3 += xv * w.w;
    }
    #pragma unroll
    for (int off = 16; off; off >>= 1) {
        a0 += __shfl_down_sync(0xffffffffu, a0, off);
        a1 += __shfl_down_sync(0xffffffffu, a1, off);
        a2 += __shfl_down_sync(0xffffffffu, a2, off);
        a3 += __shfl_down_sync(0xffffffffu, a3, off);
    }
    if (lane == 0) {
        float l[4] = {a0, a1, a2, a3};
        float m = fmaxf(fmaxf(l[0], l[1]), fmaxf(l[2], l[3]));
        float p[4], s = 0.f;
        #pragma unroll
        for (int e = 0; e < 4; e++) { p[e] = expf(l[e] - m); s += p[e]; }
        int i0 = 0; float b0 = p[0];
        #pragma unroll
        for (int e = 1; e < 4; e++) if (p[e] > b0) { b0 = p[e]; i0 = e; }
        int i1 = -1; float b1 = -1.f;
        #pragma unroll
        for (int e = 0; e < 4; e++) if (e != i0 && p[e] > b1) { b1 = p[e]; i1 = e; }

        float inv = 1.f / s;
        int pos0 = atomicAdd(&g_cnt[i0], 1);
        g_tok[i0][pos0]  = gwarp;
        g_gate[i0][pos0] = b0 * inv;
        int pos1 = atomicAdd(&g_cnt[i1], 1);
        g_tok[i1][pos1]  = gwarp;
        g_gate[i1][pos1] = b1 * inv;
    }
}

// split fp32 -> bf16 hi + bf16 lo (3-pass emulation operands)
__device__ __forceinline__ void cvt4(float4 v, __nv_bfloat16* h, __nv_bfloat16* l) {
    float a[4] = {v.x, v.y, v.z, v.w};
    #pragma unroll
    for (int t = 0; t < 4; t++) {
        __nv_bfloat16 hi = __float2bfloat16(a[t]);
        h[t] = hi;
        l[t] = __float2bfloat16(a[t] - __bfloat162float(hi));
    }
}

// ================= GEMM1: gate+up (bf16x3 tensor) + SiLU*mul epilogue =================
// BM=128, BN=64, BK=32; 256 threads = 8 warps in 4(M)x2(N); warp tile 32x32 (2x2 wmma frags)
__global__ __launch_bounds__(256) void gemm_gateup_kernel(
    const float* __restrict__ x, const float* __restrict__ Wg,
    const float* __restrict__ Wu, int e)
{
    const int ne = g_cnt[e];
    const int rb = blockIdx.x;
    if (rb * 128 >= ne) return;
    const int nb = blockIdx.y;

    __shared__ struct {
        __nv_bfloat16 Ah[128][40], Al[128][40];
        __nv_bfloat16 Bgh[32][72], Bgl[32][72];
        __nv_bfloat16 Buh[32][72], Bul[32][72];
    } s;

    const int tid  = threadIdx.x;
    const int warp = tid >> 5;
    const int wm = warp >> 1;       // 0..3
    const int wn = warp & 1;        // 0..1

    // A loader: 2 threads/row, 16 cols each
    const int ar = tid >> 1, ac = (tid & 1) * 16;
    const int* toks = g_tok[e];
    int grow = rb * 128 + ar;
    const float* aptr = x + (size_t)toks[min(grow, ne - 1)] * DD + ac;

    // B loader: 8 threads/row, 8 cols each
    const int br = tid >> 3, bc = (tid & 7) * 8;
    const float* gptr = Wg + (size_t)e * DD * FF + (size_t)br * FF + (size_t)nb * 64 + bc;
    const float* uptr = Wu + (size_t)e * DD * FF + (size_t)br * FF + (size_t)nb * 64 + bc;

    wmma::fragment<wmma::accumulator, 16, 16, 16, float> cg[2][2], cu[2][2];
    #pragma unroll
    for (int i = 0; i < 2; i++)
        #pragma unroll
        for (int j = 0; j < 2; j++) { wmma::fill_fragment(cg[i][j], 0.f); wmma::fill_fragment(cu[i][j], 0.f); }

    float4 aR[4], gR[2], uR[2];
    #pragma unroll
    for (int i = 0; i < 4; i++) aR[i] = *(const float4*)(aptr + i * 4);
    #pragma unroll
    for (int i = 0; i < 2; i++) { gR[i] = *(const float4*)(gptr + i * 4); uR[i] = *(const float4*)(uptr + i * 4); }

    for (int k0 = 0; k0 < DD; k0 += 32) {
        __syncthreads();
        #pragma unroll
        for (int i = 0; i < 4; i++) cvt4(aR[i], &s.Ah[ar][ac + i * 4], &s.Al[ar][ac + i * 4]);
        #pragma unroll
        for (int i = 0; i < 2; i++) {
            cvt4(gR[i], &s.Bgh[br][bc + i * 4], &s.Bgl[br][bc + i * 4]);
            cvt4(uR[i], &s.Buh[br][bc + i * 4], &s.Bul[br][bc + i * 4]);
        }
        __syncthreads();

        int kn = k0 + 32;
        if (kn < DD) {
            #pragma unroll
            for (int i = 0; i < 4; i++) aR[i] = *(const float4*)(aptr + kn + i * 4);
            #pragma unroll
            for (int i = 0; i < 2; i++) {
                gR[i] = *(const float4*)(gptr + (size_t)kn * FF + i * 4);
                uR[i] = *(const float4*)(uptr + (size_t)kn * FF + i * 4);
            }
        }

        #pragma unroll
        for (int ks = 0; ks < 32; ks += 16) {
            wmma::fragment<wmma::matrix_a, 16, 16, 16, __nv_bfloat16, wmma::row_major> ah[2], al[2];
            wmma::fragment<wmma::matrix_b, 16, 16, 16, __nv_bfloat16, wmma::row_major> bgh[2], bgl[2], buh[2], bul[2];
            #pragma unroll
            for (int i = 0; i < 2; i++) {
                wmma::load_matrix_sync(ah[i], &s.Ah[wm * 32 + i * 16][ks], 40);
                wmma::load_matrix_sync(al[i], &s.Al[wm * 32 + i * 16][ks], 40);
            }
            #pragma unroll
            for (int j = 0; j < 2; j++) {
                wmma::load_matrix_sync(bgh[j], &s.Bgh[ks][wn * 32 + j * 16], 72);
                wmma::load_matrix_sync(bgl[j], &s.Bgl[ks][wn * 32 + j * 16], 72);
                wmma::load_matrix_sync(buh[j], &s.Buh[ks][wn * 32 + j * 16], 72);
                wmma::load_matrix_sync(bul[j], &s.Bul[ks][wn * 32 + j * 16], 72);
            }
            #pragma unroll
            for (int i = 0; i < 2; i++)
                #pragma unroll
                for (int j = 0; j < 2; j++) {
                    wmma::mma_sync(cg[i][j], ah[i], bgh[j], cg[i][j]);
                    wmma::mma_sync(cg[i][j], ah[i], bgl[j], cg[i][j]);
                    wmma::mma_sync(cg[i][j], al[i], bgh[j], cg[i][j]);
                    wmma::mma_sync(cu[i][j], ah[i], buh[j], cu[i][j]);
                    wmma::mma_sync(cu[i][j], ah[i], bul[j], cu[i][j]);
                    wmma::mma_sync(cu[i][j], al[i], buh[j], cu[i][j]);
                }
        }
    }

    // epilogue: H = silu(g) * u ; rows >= ne get garbage-but-finite values (unused downstream)
    #pragma unroll
    for (int i = 0; i < 2; i++)
        #pragma unroll
        for (int j = 0; j < 2; j++) {
            wmma::fragment<wmma::accumulator, 16, 16, 16, float> h;
            #pragma unroll
            for (int t = 0; t < h.num_elements; t++) {
                float g = cg[i][j].x[t];
                h.x[t] = (g / (1.f + expf(-g))) * cu[i][j].x[t];
            }
            float* dst = g_H + (size_t)(rb * 128 + wm * 32 + i * 16) * FF
                             + (size_t)nb * 64 + wn * 32 + j * 16;
            wmma::store_matrix_sync(dst, h, FF, wmma::mem_row_major);
        }
}

// ================= GEMM2: down-proj (bf16x3 tensor) + gated scatter epilogue =================
__global__ __launch_bounds__(256) void gemm_down_kernel(
    const float* __restrict__ Wd, float* __restrict__ out, int e)
{
    const int ne = g_cnt[e];
    const int rb = blockIdx.x;
    if (rb * 128 >= ne) return;
    const int nb = blockIdx.y;

    __shared__ struct {
        union {
            struct {
                __nv_bfloat16 Ah[128][40], Al[128][40];
                __nv_bfloat16 Bh[32][72],  Bl[32][72];
            } t;
            float stage[128][68];
        };
    } s;

    const int tid  = threadIdx.x;
    const int warp = tid >> 5;
    const int wm = warp >> 1;
    const int wn = warp & 1;

    const int ar = tid >> 1, ac = (tid & 1) * 16;
    const float* aptr = g_H + (size_t)(rb * 128 + ar) * FF + ac;

    const int br = tid >> 3, bc = (tid & 7) * 8;
    const float* bptr = Wd + (size_t)e * FF * DD + (size_t)br * DD + (size_t)nb * 64 + bc;

    wmma::fragment<wmma::accumulator, 16, 16, 16, float> c[2][2];
    #pragma unroll
    for (int i = 0; i < 2; i++)
        #pragma unroll
        for (int j = 0; j < 2; j++) wmma::fill_fragment(c[i][j], 0.f);

    float4 aR[4], bR[2];
    #pragma unroll
    for (int i = 0; i < 4; i++) aR[i] = *(const float4*)(aptr + i * 4);
    #pragma unroll
    for (int i = 0; i < 2; i++) bR[i] = *(const float4*)(bptr + i * 4);

    for (int k0 = 0; k0 < FF; k0 += 32) {
        __syncthreads();
        #pragma unroll
        for (int i = 0; i < 4; i++) cvt4(aR[i], &s.t.Ah[ar][ac + i * 4], &s.t.Al[ar][ac + i * 4]);
        #pragma unroll
        for (int i = 0; i < 2; i++) cvt4(bR[i], &s.t.Bh[br][bc + i * 4], &s.t.Bl[br][bc + i * 4]);
        __syncthreads();

        int kn = k0 + 32;
        if (kn < FF) {
            #pragma unroll
            for (int i = 0; i < 4; i++) aR[i] = *(const float4*)(aptr + kn + i * 4);
            #pragma unroll
            for (int i = 0; i < 2; i++) bR[i] = *(const float4*)(bptr + (size_t)kn * DD + i * 4);
        }

        #pragma unroll
        for (int ks = 0; ks < 32; ks += 16) {
            wmma::fragment<wmma::matrix_a, 16, 16, 16, __nv_bfloat16, wmma::row_major> ah[2], al[2];
            wmma::fragment<wmma::matrix_b, 16, 16, 16, __nv_bfloat16, wmma::row_major> bh[2], bl[2];
            #pragma unroll
            for (int i = 0; i < 2; i++) {
                wmma::load_matrix_sync(ah[i], &s.t.Ah[wm * 32 + i * 16][ks], 40);
                wmma::load_matrix_sync(al[i], &s.t.Al[wm * 32 + i * 16][ks], 40);
            }
            #pragma unroll
            for (int j = 0; j < 2; j++) {
                wmma::load_matrix_sync(bh[j], &s.t.Bh[ks][wn * 32 + j * 16], 72);
                wmma::load_matrix_sync(bl[j], &s.t.Bl[ks][wn * 32 + j * 16], 72);
            }
            #pragma unroll
            for (int i = 0; i < 2; i++)
                #pragma unroll
                for (int j = 0; j < 2; j++) {
                    wmma::mma_sync(c[i][j], ah[i], bh[j], c[i][j]);
                    wmma::mma_sync(c[i][j], ah[i], bl[j], c[i][j]);
                    wmma::mma_sync(c[i][j], al[i], bh[j], c[i][j]);
                }
        }
    }

    // stage to smem, then gated accumulate into out (expert kernels are stream-serialized:
    // no concurrent writers to a token row -> plain read-modify-write, no atomics)
    __syncthreads();
    #pragma unroll
    for (int i = 0; i < 2; i++)
        #pragma unroll
        for (int j = 0; j < 2; j++)
            wmma::store_matrix_sync(&s.stage[wm * 32 + i * 16][wn * 32 + j * 16], c[i][j], 68, wmma::mem_row_major);
    __syncthreads();

    const int r  = tid >> 1;
    const int c0 = (tid & 1) * 32;
    const int growo = rb * 128 + r;
    if (growo < ne) {
        int   tok = g_tok[e][growo];
        float gv  = g_gate[e][growo];
        float* orow = out + (size_t)tok * DD + (size_t)nb * 64 + c0;
        #pragma unroll
        for (int q = 0; q < 8; q++) {
            float4 o = *(float4*)(orow + q * 4);
            o.x += s.stage[r][c0 + q * 4 + 0] * gv;
            o.y += s.stage[r][c0 + q * 4 + 1] * gv;
            o.z += s.stage[r][c0 + q * 4 + 2] * gv;
            o.w += s.stage[r][c0 + q * 4 + 3] * gv;
            *(float4*)(orow + q * 4) = o;
        }
    }
}

// ---------------- launch ----------------
extern "C" void kernel_launch(void* const* d_in, const int* in_sizes, int n_in,
                              void* d_out, int out_size) {
    const float* x  = (const float*)d_in[0];
    const float* Wr = (const float*)d_in[1];
    const float* Wg = (const float*)d_in[2];
    const float* Wu = (const float*)d_in[3];
    const float* Wd = (const float*)d_in[4];
    float* out = (float*)d_out;

    const int n_out = NT * DD;
    init_kernel<<<(n_out + 255) / 256, 256>>>(out, n_out);
    router_kernel<<<(NT * 32 + 127) / 128, 128>>>(x, Wr);

    for (int e = 0; e < EE; e++) {
        // grid.x = row-block (16 worst case), grid.y = n-block: consecutive blocks share
        // the same weight slab (L2 reuse), different row-blocks.
        gemm_gateup_kernel<<<dim3(16, FF / 64), 256>>>(x, Wg, Wu, e);
        gemm_down_kernel<<<dim3(16, DD / 64), 256>>>(Wd, out, e);
    }
}

// round 8
// speedup vs baseline: 1.9858x; 1.4759x over previous
#include <cuda_runtime.h>
#include <cuda_bf16.h>
#include <mma.h>
#include <math.h>
#include <cstdint>

using namespace nvcuda;

// Problem constants
#define BB 2
#define SS 1024
#define DD 2048
#define FF 8192
#define EE 4
#define NT (BB*SS)            // 2048 tokens
#define WSZ ((size_t)EE*DD*FF)

// ---------------- device scratch (no allocations allowed) ----------------
__device__ int   g_cnt[EE];
__device__ int   g_tok[EE][NT];
__device__ float g_gate[EE][NT];
// pre-split bf16 hi/lo planes
__device__ __nv_bfloat16 g_Wg_hi[WSZ], g_Wg_lo[WSZ];
__device__ __nv_bfloat16 g_Wu_hi[WSZ], g_Wu_lo[WSZ];
__device__ __nv_bfloat16 g_Wd_hi[WSZ], g_Wd_lo[WSZ];
__device__ __nv_bfloat16 g_x_hi[(size_t)NT*DD], g_x_lo[(size_t)NT*DD];
__device__ __nv_bfloat16 g_Hh[(size_t)NT*FF],  g_Hl[(size_t)NT*FF];

// ---------------- helpers ----------------
__device__ __forceinline__ uint32_t smem_u32(const void* p) {
    uint32_t a;
    asm("{ .reg .u64 t; cvta.to.shared.u64 t, %1; cvt.u32.u64 %0, t; }" : "=r"(a) : "l"(p));
    return a;
}
__device__ __forceinline__ void cpa16(uint32_t dst, const void* src) {
    asm volatile("{ .reg .u64 g; cvta.to.global.u64 g, %1; cp.async.cg.shared.global [%0], [g], 16; }"
                 :: "r"(dst), "l"(src) : "memory");
}
#define CPA_COMMIT() asm volatile("cp.async.commit_group;" ::: "memory")
#define CPA_WAIT1()  asm volatile("cp.async.wait_group 1;" ::: "memory")
#define CPA_WAIT0()  asm volatile("cp.async.wait_group 0;" ::: "memory")

__device__ __forceinline__ void split1(float v, unsigned short& h, unsigned short& l) {
    __nv_bfloat16 hb = __float2bfloat16(v);
    h = __bfloat16_as_ushort(hb);
    l = __bfloat16_as_ushort(__float2bfloat16(v - __bfloat162float(hb)));
}
__device__ __forceinline__ unsigned int pk2(unsigned short a, unsigned short b) {
    return (unsigned int)a | ((unsigned int)b << 16);
}

// ---------------- init / split / router ----------------
__global__ void init_kernel(float* __restrict__ out, int n) {
    int i = blockIdx.x * blockDim.x + threadIdx.x;
    if (i < n) out[i] = 0.0f;
    if (i < EE) g_cnt[i] = 0;
}

__global__ void split_kernel(const float* __restrict__ src, __nv_bfloat16* __restrict__ hi,
                             __nv_bfloat16* __restrict__ lo, size_t n4) {
    size_t i = (size_t)blockIdx.x * blockDim.x + threadIdx.x;
    if (i >= n4) return;
    float4 v = *(const float4*)(src + i * 4);
    float a[4] = {v.x, v.y, v.z, v.w};
    unsigned short h[4], l[4];
    #pragma unroll
    for (int t = 0; t < 4; t++) split1(a[t], h[t], l[t]);
    *(uint2*)(hi + i * 4) = make_uint2(pk2(h[0], h[1]), pk2(h[2], h[3]));
    *(uint2*)(lo + i * 4) = make_uint2(pk2(l[0], l[1]), pk2(l[2], l[3]));
}

__global__ void router_kernel(const float* __restrict__ x, const float* __restrict__ Wr) {
    int gwarp = (blockIdx.x * blockDim.x + threadIdx.x) >> 5;
    int lane  = threadIdx.x & 31;
    if (gwarp >= NT) return;
    const float* xr = x + (size_t)gwarp * DD;
    float a0 = 0.f, a1 = 0.f, a2 = 0.f, a3 = 0.f;
    for (int d = lane; d < DD; d += 32) {
        float xv = xr[d];
        float4 w = *(const float4*)(Wr + (size_t)d * 4);
        a0 += xv * w.x; a1 += xv * w.y; a2 += xv * w.z; a3 += xv * w.w;
    }
    #pragma unroll
    for (int off = 16; off; off >>= 1) {
        a0 += __shfl_down_sync(0xffffffffu, a0, off);
        a1 += __shfl_down_sync(0xffffffffu, a1, off);
        a2 += __shfl_down_sync(0xffffffffu, a2, off);
        a3 += __shfl_down_sync(0xffffffffu, a3, off);
    }
    if (lane == 0) {
        float l[4] = {a0, a1, a2, a3};
        float m = fmaxf(fmaxf(l[0], l[1]), fmaxf(l[2], l[3]));
        float p[4], s = 0.f;
        #pragma unroll
        for (int e = 0; e < 4; e++) { p[e] = expf(l[e] - m); s += p[e]; }
        int i0 = 0; float b0 = p[0];
        #pragma unroll
        for (int e = 1; e < 4; e++) if (p[e] > b0) { b0 = p[e]; i0 = e; }
        int i1 = -1; float b1 = -1.f;
        #pragma unroll
        for (int e = 0; e < 4; e++) if (e != i0 && p[e] > b1) { b1 = p[e]; i1 = e; }
        float inv = 1.f / s;
        int pos0 = atomicAdd(&g_cnt[i0], 1);
        g_tok[i0][pos0] = gwarp; g_gate[i0][pos0] = b0 * inv;
        int pos1 = atomicAdd(&g_cnt[i1], 1);
        g_tok[i1][pos1] = gwarp; g_gate[i1][pos1] = b1 * inv;
    }
}

// ================= smem layout constants =================
// A tiles: [128][40] bf16 (10240 B, row stride 80 B)
// B tiles: [32][136] bf16 (8704 B, row stride 272 B)
#define A_BYTES 10240
#define B_BYTES 8704
#define DN_STG  (2*A_BYTES + 2*B_BYTES)              // 37888
#define GU_STG  (2*A_BYTES + 4*B_BYTES)              // 55296
#define DN_SMEM (2*DN_STG)                           // 75776
#define GU_SMEM (2*GU_STG)                           // 110592

typedef wmma::fragment<wmma::matrix_a, 16, 16, 16, __nv_bfloat16, wmma::row_major> FragA;
typedef wmma::fragment<wmma::matrix_b, 16, 16, 16, __nv_bfloat16, wmma::row_major> FragB;
typedef wmma::fragment<wmma::accumulator, 16, 16, 16, float> FragC;

// ================= GEMM1: gate+up (bf16x3 HMMA) + SiLU*mul -> H hi/lo =================
// block 128x128, k=32, 2-stage cp.async; 8 warps = 2(M)x4(N); warp tile 64x32
__global__ __launch_bounds__(256, 1) void gemm_gateup(int e)
{
    const int ne = g_cnt[e];
    const int rb = blockIdx.x;
    if (rb * 128 >= ne) return;
    const int nb = blockIdx.y;

    extern __shared__ char smem[];
    const uint32_t sb = smem_u32(smem);
    const int tid  = threadIdx.x;
    const int warp = tid >> 5;
    const int wm = warp >> 2;        // 0..1
    const int wn = warp & 3;         // 0..3

    // loader mappings
    const int arow = tid >> 1, acol = (tid & 1) * 16;
    const int tok  = g_tok[e][min(rb * 128 + arow, ne - 1)];
    const __nv_bfloat16* sAh = g_x_hi + (size_t)tok * DD + acol;
    const __nv_bfloat16* sAl = g_x_lo + (size_t)tok * DD + acol;
    const uint32_t dA = sb + (uint32_t)arow * 80 + acol * 2;

    const int brow = tid >> 3, bcol = (tid & 7) * 16;
    const size_t wb = (size_t)e * DD * FF + (size_t)brow * FF + (size_t)nb * 128 + bcol;
    const __nv_bfloat16* sGh = g_Wg_hi + wb;
    const __nv_bfloat16* sGl = g_Wg_lo + wb;
    const __nv_bfloat16* sUh = g_Wu_hi + wb;
    const __nv_bfloat16* sUl = g_Wu_lo + wb;
    const uint32_t dB = sb + 2 * A_BYTES + (uint32_t)brow * 272 + bcol * 2;

    #define GU_LOAD(st, k) do { \
        uint32_t o = (uint32_t)(st) * GU_STG; size_t kf = (size_t)(k) * FF; \
        cpa16(dA + o,                sAh + (k));  cpa16(dA + o + 16,                sAh + (k) + 8); \
        cpa16(dA + o + A_BYTES,      sAl + (k));  cpa16(dA + o + A_BYTES + 16,      sAl + (k) + 8); \
        cpa16(dB + o,                sGh + kf);   cpa16(dB + o + 16,                sGh + kf + 8); \
        cpa16(dB + o + B_BYTES,      sGl + kf);   cpa16(dB + o + B_BYTES + 16,      sGl + kf + 8); \
        cpa16(dB + o + 2*B_BYTES,    sUh + kf);   cpa16(dB + o + 2*B_BYTES + 16,    sUh + kf + 8); \
        cpa16(dB + o + 3*B_BYTES,    sUl + kf);   cpa16(dB + o + 3*B_BYTES + 16,    sUl + kf + 8); \
    } while (0)

    FragC cg[4][2], cu[4][2];
    #pragma unroll
    for (int m = 0; m < 4; m++)
        #pragma unroll
        for (int n = 0; n < 2; n++) { wmma::fill_fragment(cg[m][n], 0.f); wmma::fill_fragment(cu[m][n], 0.f); }

    GU_LOAD(0, 0);  CPA_COMMIT();
    GU_LOAD(1, 32); CPA_COMMIT();

    const int NS = DD / 32;   // 64
    #pragma unroll 1
    for (int s = 0; s < NS; s++) {
        if (s + 1 < NS) CPA_WAIT1(); else CPA_WAIT0();
        __syncthreads();

        const char* base = smem + (s & 1) * GU_STG;
        const __nv_bfloat16* Ah = (const __nv_bfloat16*)(base);
        const __nv_bfloat16* Al = (const __nv_bfloat16*)(base + A_BYTES);
        const __nv_bfloat16* Gh = (const __nv_bfloat16*)(base + 2 * A_BYTES);
        const __nv_bfloat16* Gl = (const __nv_bfloat16*)(base + 2 * A_BYTES + B_BYTES);
        const __nv_bfloat16* Uh = (const __nv_bfloat16*)(base + 2 * A_BYTES + 2 * B_BYTES);
        const __nv_bfloat16* Ul = (const __nv_bfloat16*)(base + 2 * A_BYTES + 3 * B_BYTES);

        #pragma unroll
        for (int ks = 0; ks < 32; ks += 16) {
            FragA ah[4], al[4];
            #pragma unroll
            for (int m = 0; m < 4; m++) {
                wmma::load_matrix_sync(ah[m], Ah + (wm * 64 + m * 16) * 40 + ks, 40);
                wmma::load_matrix_sync(al[m], Al + (wm * 64 + m * 16) * 40 + ks, 40);
            }
            #pragma unroll
            for (int n = 0; n < 2; n++) {
                const int nc = wn * 32 + n * 16;
                FragB bgh, bgl, buh, bul;
                wmma::load_matrix_sync(bgh, Gh + ks * 136 + nc, 136);
                wmma::load_matrix_sync(bgl, Gl + ks * 136 + nc, 136);
                wmma::load_matrix_sync(buh, Uh + ks * 136 + nc, 136);
                wmma::load_matrix_sync(bul, Ul + ks * 136 + nc, 136);
                #pragma unroll
                for (int m = 0; m < 4; m++) {
                    wmma::mma_sync(cg[m][n], ah[m], bgh, cg[m][n]);
                    wmma::mma_sync(cg[m][n], ah[m], bgl, cg[m][n]);
                    wmma::mma_sync(cg[m][n], al[m], bgh, cg[m][n]);
                    wmma::mma_sync(cu[m][n], ah[m], buh, cu[m][n]);
                    wmma::mma_sync(cu[m][n], ah[m], bul, cu[m][n]);
                    wmma::mma_sync(cu[m][n], al[m], buh, cu[m][n]);
                }
            }
        }
        __syncthreads();
        if (s + 2 < NS) { GU_LOAD(s & 1, (s + 2) * 32); CPA_COMMIT(); }
    }

    // epilogue: h = silu(g)*u -> fp32 smem stage -> split bf16 hi/lo -> g_Hh/g_Hl
    float* stg = (float*)smem;
    #pragma unroll
    for (int m = 0; m < 4; m++)
        #pragma unroll
        for (int n = 0; n < 2; n++) {
            #pragma unroll
            for (int t = 0; t < cg[m][n].num_elements; t++) {
                float g = cg[m][n].x[t];
                cg[m][n].x[t] = (g / (1.f + expf(-g))) * cu[m][n].x[t];
            }
            wmma::store_matrix_sync(stg + (wm * 64 + m * 16) * 132 + wn * 32 + n * 16,
                                    cg[m][n], 132, wmma::mem_row_major);
        }
    __syncthreads();
    {
        const int r = tid >> 1, c0 = (tid & 1) * 64;
        __nv_bfloat16* hh = g_Hh + (size_t)(rb * 128 + r) * FF + (size_t)nb * 128 + c0;
        __nv_bfloat16* hl = g_Hl + (size_t)(rb * 128 + r) * FF + (size_t)nb * 128 + c0;
        #pragma unroll
        for (int q = 0; q < 8; q++) {
            unsigned short hv[8], lv[8];
            #pragma unroll
            for (int j = 0; j < 8; j++) split1(stg[r * 132 + c0 + q * 8 + j], hv[j], lv[j]);
            *(uint4*)(hh + q * 8) = make_uint4(pk2(hv[0],hv[1]), pk2(hv[2],hv[3]), pk2(hv[4],hv[5]), pk2(hv[6],hv[7]));
            *(uint4*)(hl + q * 8) = make_uint4(pk2(lv[0],lv[1]), pk2(lv[2],lv[3]), pk2(lv[4],lv[5]), pk2(lv[6],lv[7]));
        }
    }
    #undef GU_LOAD
}

// ================= GEMM2: down-proj (bf16x3 HMMA) + gated accumulate =================
__global__ __launch_bounds__(256, 1) void gemm_down(float* __restrict__ out, int e)
{
    const int ne = g_cnt[e];
    const int rb = blockIdx.x;
    if (rb * 128 >= ne) return;
    const int nb = blockIdx.y;

    extern __shared__ char smem[];
    const uint32_t sb = smem_u32(smem);
    const int tid  = threadIdx.x;
    const int warp = tid >> 5;
    const int wm = warp >> 2;
    const int wn = warp & 3;

    const int arow = tid >> 1, acol = (tid & 1) * 16;
    const __nv_bfloat16* sAh = g_Hh + (size_t)(rb * 128 + arow) * FF + acol;
    const __nv_bfloat16* sAl = g_Hl + (size_t)(rb * 128 + arow) * FF + acol;
    const uint32_t dA = sb + (uint32_t)arow * 80 + acol * 2;

    const int brow = tid >> 3, bcol = (tid & 7) * 16;
    const size_t wb = (size_t)e * FF * DD + (size_t)brow * DD + (size_t)nb * 128 + bcol;
    const __nv_bfloat16* sBh = g_Wd_hi + wb;
    const __nv_bfloat16* sBl = g_Wd_lo + wb;
    const uint32_t dB = sb + 2 * A_BYTES + (uint32_t)brow * 272 + bcol * 2;

    #define DN_LOAD(st, k) do { \
        uint32_t o = (uint32_t)(st) * DN_STG; size_t kf = (size_t)(k) * DD; \
        cpa16(dA + o,           sAh + (k)); cpa16(dA + o + 16,           sAh + (k) + 8); \
        cpa16(dA + o + A_BYTES, sAl + (k)); cpa16(dA + o + A_BYTES + 16, sAl + (k) + 8); \
        cpa16(dB + o,           sBh + kf);  cpa16(dB + o + 16,           sBh + kf + 8); \
        cpa16(dB + o + B_BYTES, sBl + kf);  cpa16(dB + o + B_BYTES + 16, sBl + kf + 8); \
    } while (0)

    FragC c[4][2];
    #pragma unroll
    for (int m = 0; m < 4; m++)
        #pragma unroll
        for (int n = 0; n < 2; n++) wmma::fill_fragment(c[m][n], 0.f);

    DN_LOAD(0, 0);  CPA_COMMIT();
    DN_LOAD(1, 32); CPA_COMMIT();

    const int NS = FF / 32;   // 256
    #pragma unroll 1
    for (int s = 0; s < NS; s++) {
        if (s + 1 < NS) CPA_WAIT1(); else CPA_WAIT0();
        __syncthreads();

        const char* base = smem + (s & 1) * DN_STG;
        const __nv_bfloat16* Ah = (const __nv_bfloat16*)(base);
        const __nv_bfloat16* Al = (const __nv_bfloat16*)(base + A_BYTES);
        const __nv_bfloat16* Bh = (const __nv_bfloat16*)(base + 2 * A_BYTES);
        const __nv_bfloat16* Bl = (const __nv_bfloat16*)(base + 2 * A_BYTES + B_BYTES);

        #pragma unroll
        for (int ks = 0; ks < 32; ks += 16) {
            FragA ah[4], al[4];
            #pragma unroll
            for (int m = 0; m < 4; m++) {
                wmma::load_matrix_sync(ah[m], Ah + (wm * 64 + m * 16) * 40 + ks, 40);
                wmma::load_matrix_sync(al[m], Al + (wm * 64 + m * 16) * 40 + ks, 40);
            }
            #pragma unroll
            for (int n = 0; n < 2; n++) {
                const int nc = wn * 32 + n * 16;
                FragB bh, bl;
                wmma::load_matrix_sync(bh, Bh + ks * 136 + nc, 136);
                wmma::load_matrix_sync(bl, Bl + ks * 136 + nc, 136);
                #pragma unroll
                for (int m = 0; m < 4; m++) {
                    wmma::mma_sync(c[m][n], ah[m], bh, c[m][n]);
                    wmma::mma_sync(c[m][n], ah[m], bl, c[m][n]);
                    wmma::mma_sync(c[m][n], al[m], bh, c[m][n]);
                }
            }
        }
        __syncthreads();
        if (s + 2 < NS) { DN_LOAD(s & 1, (s + 2) * 32); CPA_COMMIT(); }
    }

    // epilogue: stage fp32, then out[tok] += gv * val (experts stream-serialized: no atomics)
    float* stg = (float*)smem;
    #pragma unroll
    for (int m = 0; m < 4; m++)
        #pragma unroll
        for (int n = 0; n < 2; n++)
            wmma::store_matrix_sync(stg + (wm * 64 + m * 16) * 132 + wn * 32 + n * 16,
                                    c[m][n], 132, wmma::mem_row_major);
    __syncthreads();
    {
        const int r = tid >> 1, c0 = (tid & 1) * 64;
        const int grow = rb * 128 + r;
        if (grow < ne) {
            const int   tok = g_tok[e][grow];
            const float gv  = g_gate[e][grow];
            float* orow = out + (size_t)tok * DD + (size_t)nb * 128 + c0;
            #pragma unroll
            for (int q = 0; q < 16; q++) {
                float4 o = *(float4*)(orow + q * 4);
                o.x += gv * stg[r * 132 + c0 + q * 4 + 0];
                o.y += gv * stg[r * 132 + c0 + q * 4 + 1];
                o.z += gv * stg[r * 132 + c0 + q * 4 + 2];
                o.w += gv * stg[r * 132 + c0 + q * 4 + 3];
                *(float4*)(orow + q * 4) = o;
            }
        }
    }
    #undef DN_LOAD
}

// ---------------- launch ----------------
extern "C" void kernel_launch(void* const* d_in, const int* in_sizes, int n_in,
                              void* d_out, int out_size) {
    const float* x  = (const float*)d_in[0];
    const float* Wr = (const float*)d_in[1];
    const float* Wg = (const float*)d_in[2];
    const float* Wu = (const float*)d_in[3];
    const float* Wd = (const float*)d_in[4];
    float* out = (float*)d_out;

    static int attr_done = 0;
    if (!attr_done) {
        cudaFuncSetAttribute(gemm_gateup, cudaFuncAttributeMaxDynamicSharedMemorySize, GU_SMEM);
        cudaFuncSetAttribute(gemm_down,   cudaFuncAttributeMaxDynamicSharedMemorySize, DN_SMEM);
        attr_done = 1;
    }

    const int n_out = NT * DD;
    init_kernel<<<(n_out + 255) / 256, 256>>>(out, n_out);

    // pre-split weights + x into bf16 hi/lo planes
    {
        __nv_bfloat16 *wg_h, *wg_l, *wu_h, *wu_l, *wd_h, *wd_l, *x_h, *x_l;
        cudaGetSymbolAddress((void**)&wg_h, g_Wg_hi); cudaGetSymbolAddress((void**)&wg_l, g_Wg_lo);
        cudaGetSymbolAddress((void**)&wu_h, g_Wu_hi); cudaGetSymbolAddress((void**)&wu_l, g_Wu_lo);
        cudaGetSymbolAddress((void**)&wd_h, g_Wd_hi); cudaGetSymbolAddress((void**)&wd_l, g_Wd_lo);
        cudaGetSymbolAddress((void**)&x_h,  g_x_hi);  cudaGetSymbolAddress((void**)&x_l,  g_x_lo);
        size_t w4 = WSZ / 4;
        split_kernel<<<(unsigned)((w4 + 255) / 256), 256>>>(Wg, wg_h, wg_l, w4);
        split_kernel<<<(unsigned)((w4 + 255) / 256), 256>>>(Wu, wu_h, wu_l, w4);
        split_kernel<<<(unsigned)((w4 + 255) / 256), 256>>>(Wd, wd_h, wd_l, w4);
        size_t x4 = (size_t)NT * DD / 4;
        split_kernel<<<(unsigned)((x4 + 255) / 256), 256>>>(x, x_h, x_l, x4);
    }

    router_kernel<<<(NT * 32 + 127) / 128, 128>>>(x, Wr);

    for (int e = 0; e < EE; e++) {
        // blockIdx.x = row-block (fastest) -> blocks sharing a weight slab run together (L2 reuse)
        gemm_gateup<<<dim3(16, FF / 128), 256, GU_SMEM>>>(e);
        gemm_down  <<<dim3(16, DD / 128), 256, DN_SMEM>>>(out, e);
    }
}

// round 9
// speedup vs baseline: 2.2413x; 1.1286x over previous
#include <cuda_runtime.h>
#include <cuda_bf16.h>
#include <mma.h>
#include <math.h>
#include <cstdint>

using namespace nvcuda;

// Problem constants
#define BB 2
#define SS 1024
#define DD 2048
#define FF 8192
#define EE 4
#define NT (BB*SS)            // 2048 tokens
#define WSZ ((size_t)EE*DD*FF)
#define HROWS ((size_t)EE*2048)

// ---------------- device scratch (no allocations allowed) ----------------
__device__ int   g_cnt[EE];
__device__ int   g_tok[EE][NT];
__device__ float g_gate[EE][NT];
// pre-split bf16 hi/lo planes
__device__ __nv_bfloat16 g_Wg_hi[WSZ], g_Wg_lo[WSZ];
__device__ __nv_bfloat16 g_Wu_hi[WSZ], g_Wu_lo[WSZ];
__device__ __nv_bfloat16 g_Wd_hi[WSZ], g_Wd_lo[WSZ];
__device__ __nv_bfloat16 g_x_hi[(size_t)NT*DD], g_x_lo[(size_t)NT*DD];
__device__ __nv_bfloat16 g_Hh[HROWS*FF], g_Hl[HROWS*FF];

// ---------------- helpers ----------------
__device__ __forceinline__ uint32_t smem_u32(const void* p) {
    uint32_t a;
    asm("{ .reg .u64 t; cvta.to.shared.u64 t, %1; cvt.u32.u64 %0, t; }" : "=r"(a) : "l"(p));
    return a;
}
__device__ __forceinline__ void cpa16(uint32_t dst, const void* src) {
    asm volatile("{ .reg .u64 g; cvta.to.global.u64 g, %1; cp.async.cg.shared.global [%0], [g], 16; }"
                 :: "r"(dst), "l"(src) : "memory");
}
#define CPA_COMMIT() asm volatile("cp.async.commit_group;" ::: "memory")
#define CPA_WAIT1()  asm volatile("cp.async.wait_group 1;" ::: "memory")
#define CPA_WAIT0()  asm volatile("cp.async.wait_group 0;" ::: "memory")

__device__ __forceinline__ void split1(float v, unsigned short& h, unsigned short& l) {
    __nv_bfloat16 hb = __float2bfloat16(v);
    h = __bfloat16_as_ushort(hb);
    l = __bfloat16_as_ushort(__float2bfloat16(v - __bfloat162float(hb)));
}
__device__ __forceinline__ unsigned int pk2(unsigned short a, unsigned short b) {
    return (unsigned int)a | ((unsigned int)b << 16);
}

// ---------------- init / split / router ----------------
__global__ void init_kernel(float* __restrict__ out, int n) {
    int i = blockIdx.x * blockDim.x + threadIdx.x;
    if (i < n) out[i] = 0.0f;
    if (i < EE) g_cnt[i] = 0;
}

__global__ void split_kernel(const float* __restrict__ src, __nv_bfloat16* __restrict__ hi,
                             __nv_bfloat16* __restrict__ lo, size_t n4) {
    size_t i = (size_t)blockIdx.x * blockDim.x + threadIdx.x;
    if (i >= n4) return;
    float4 v = *(const float4*)(src + i * 4);
    float a[4] = {v.x, v.y, v.z, v.w};
    unsigned short h[4], l[4];
    #pragma unroll
    for (int t = 0; t < 4; t++) split1(a[t], h[t], l[t]);
    *(uint2*)(hi + i * 4) = make_uint2(pk2(h[0], h[1]), pk2(h[2], h[3]));
    *(uint2*)(lo + i * 4) = make_uint2(pk2(l[0], l[1]), pk2(l[2], l[3]));
}

__global__ void router_kernel(const float* __restrict__ x, const float* __restrict__ Wr) {
    int gwarp = (blockIdx.x * blockDim.x + threadIdx.x) >> 5;
    int lane  = threadIdx.x & 31;
    if (gwarp >= NT) return;
    const float* xr = x + (size_t)gwarp * DD;
    float a0 = 0.f, a1 = 0.f, a2 = 0.f, a3 = 0.f;
    for (int d = lane; d < DD; d += 32) {
        float xv = xr[d];
        float4 w = *(const float4*)(Wr + (size_t)d * 4);
        a0 += xv * w.x; a1 += xv * w.y; a2 += xv * w.z; a3 += xv * w.w;
    }
    #pragma unroll
    for (int off = 16; off; off >>= 1) {
        a0 += __shfl_down_sync(0xffffffffu, a0, off);
        a1 += __shfl_down_sync(0xffffffffu, a1, off);
        a2 += __shfl_down_sync(0xffffffffu, a2, off);
        a3 += __shfl_down_sync(0xffffffffu, a3, off);
    }
    if (lane == 0) {
        float l[4] = {a0, a1, a2, a3};
        float m = fmaxf(fmaxf(l[0], l[1]), fmaxf(l[2], l[3]));
        float p[4], s = 0.f;
        #pragma unroll
        for (int e = 0; e < 4; e++) { p[e] = expf(l[e] - m); s += p[e]; }
        int i0 = 0; float b0 = p[0];
        #pragma unroll
        for (int e = 1; e < 4; e++) if (p[e] > b0) { b0 = p[e]; i0 = e; }
        int i1 = -1; float b1 = -1.f;
        #pragma unroll
        for (int e = 0; e < 4; e++) if (e != i0 && p[e] > b1) { b1 = p[e]; i1 = e; }
        float inv = 1.f / s;
        int pos0 = atomicAdd(&g_cnt[i0], 1);
        g_tok[i0][pos0] = gwarp; g_gate[i0][pos0] = b0 * inv;
        int pos1 = atomicAdd(&g_cnt[i1], 1);
        g_tok[i1][pos1] = gwarp; g_gate[i1][pos1] = b1 * inv;
    }
}

// ================= smem layout =================
// A rows: 40 halfs stride (80 B). B rows: 136 halfs stride (272 B).
#define GU_AB   10240                  // A plane [128][40]
#define GU_BB   8704                   // B plane [32][136]
#define GU_STG  (2*GU_AB + 4*GU_BB)    // 55296
#define GU_SMEM (2*GU_STG)             // 110592

#define DN_AB   20480                  // A plane [256][40]
#define DN_BB   8704                   // B plane [32][136]
#define DN_STG  (2*DN_AB + 2*DN_BB)    // 58368
#define DN_SMEM (2*DN_STG)             // 116736

typedef wmma::fragment<wmma::matrix_a, 16, 16, 16, __nv_bfloat16, wmma::row_major> FragA;
typedef wmma::fragment<wmma::matrix_b, 16, 16, 16, __nv_bfloat16, wmma::row_major> FragB;
typedef wmma::fragment<wmma::accumulator, 16, 16, 16, float> FragC;

// ================= GEMM1: gate+up (bf16x3 HMMA) + SiLU*mul -> H hi/lo =================
// BM=128, BN=128 per matrix (G and U both), BK=32, 512 threads = 16 warps:
// wm = warp>>3 (2), mat = (warp>>2)&1, wn = warp&3 (4); warp tile 64x32 of its matrix.
__global__ __launch_bounds__(512, 1) void gemm_gateup()
{
    const int e  = blockIdx.x >> 4;
    const int rb = blockIdx.x & 15;
    const int ne = g_cnt[e];
    if (rb * 128 >= ne) return;
    const int nb = blockIdx.y;

    extern __shared__ char smem[];
    const uint32_t sb = smem_u32(smem);
    const int tid  = threadIdx.x;
    const int warp = tid >> 5;
    const int wm   = warp >> 3;
    const int mat  = (warp >> 2) & 1;
    const int wn   = warp & 3;

    // A loader: 128 rows x 4 chunks(8 halfs) -> 512 slots
    const int arow = tid >> 2, achk = (tid & 3) * 8;
    const int tok  = g_tok[e][min(rb * 128 + arow, ne - 1)];
    const __nv_bfloat16* sAh = g_x_hi + (size_t)tok * DD + achk;
    const __nv_bfloat16* sAl = g_x_lo + (size_t)tok * DD + achk;
    const uint32_t dA = sb + (uint32_t)arow * 80 + achk * 2;

    // B loader: 32 rows x 16 chunks -> 512 slots, 4 planes
    const int brow = tid >> 4, bchk = (tid & 15) * 8;
    const size_t wb = (size_t)e * DD * FF + (size_t)brow * FF + (size_t)nb * 128 + bchk;
    const __nv_bfloat16* sGh = g_Wg_hi + wb;
    const __nv_bfloat16* sGl = g_Wg_lo + wb;
    const __nv_bfloat16* sUh = g_Wu_hi + wb;
    const __nv_bfloat16* sUl = g_Wu_lo + wb;
    const uint32_t dB = sb + 2 * GU_AB + (uint32_t)brow * 272 + bchk * 2;

    #define GU_LOAD(st, k) do { \
        uint32_t o = (uint32_t)(st) * GU_STG; size_t kf = (size_t)(k) * FF; \
        cpa16(dA + o,          sAh + (k)); \
        cpa16(dA + o + GU_AB,  sAl + (k)); \
        cpa16(dB + o,            sGh + kf); \
        cpa16(dB + o + GU_BB,    sGl + kf); \
        cpa16(dB + o + 2*GU_BB,  sUh + kf); \
        cpa16(dB + o + 3*GU_BB,  sUl + kf); \
    } while (0)

    FragC c[4][2];
    #pragma unroll
    for (int m = 0; m < 4; m++)
        #pragma unroll
        for (int n = 0; n < 2; n++) wmma::fill_fragment(c[m][n], 0.f);

    GU_LOAD(0, 0);  CPA_COMMIT();
    GU_LOAD(1, 32); CPA_COMMIT();

    const int NS = DD / 32;   // 64
    #pragma unroll 1
    for (int s = 0; s < NS; s++) {
        if (s + 1 < NS) CPA_WAIT1(); else CPA_WAIT0();
        __syncthreads();

        const char* base = smem + (s & 1) * GU_STG;
        const __nv_bfloat16* Ah = (const __nv_bfloat16*)(base);
        const __nv_bfloat16* Al = (const __nv_bfloat16*)(base + GU_AB);
        const __nv_bfloat16* Bh = (const __nv_bfloat16*)(base + 2 * GU_AB + (mat ? 2 * GU_BB : 0));
        const __nv_bfloat16* Bl = (const __nv_bfloat16*)(base + 2 * GU_AB + (mat ? 3 * GU_BB : GU_BB));

        #pragma unroll
        for (int ks = 0; ks < 32; ks += 16) {
            FragA ah[4], al[4];
            #pragma unroll
            for (int m = 0; m < 4; m++) {
                wmma::load_matrix_sync(ah[m], Ah + (wm * 64 + m * 16) * 40 + ks, 40);
                wmma::load_matrix_sync(al[m], Al + (wm * 64 + m * 16) * 40 + ks, 40);
            }
            #pragma unroll
            for (int n = 0; n < 2; n++) {
                const int nc = wn * 32 + n * 16;
                FragB bh, bl;
                wmma::load_matrix_sync(bh, Bh + ks * 136 + nc, 136);
                wmma::load_matrix_sync(bl, Bl + ks * 136 + nc, 136);
                #pragma unroll
                for (int m = 0; m < 4; m++) {
                    wmma::mma_sync(c[m][n], ah[m], bh, c[m][n]);
                    wmma::mma_sync(c[m][n], ah[m], bl, c[m][n]);
                    wmma::mma_sync(c[m][n], al[m], bh, c[m][n]);
                }
            }
        }
        __syncthreads();
        if (s + 2 < NS) { GU_LOAD(s & 1, (s + 2) * 32); CPA_COMMIT(); }
    }

    // epilogue: two-pass via fp32 stage [128][132]
    float* stg = (float*)smem;
    const int er = tid >> 2, ec0 = (tid & 3) * 32;

    if (mat == 0) {
        #pragma unroll
        for (int m = 0; m < 4; m++)
            #pragma unroll
            for (int n = 0; n < 2; n++)
                wmma::store_matrix_sync(stg + (wm * 64 + m * 16) * 132 + wn * 32 + n * 16,
                                        c[m][n], 132, wmma::mem_row_major);
    }
    __syncthreads();
    float gv[32];
    #pragma unroll
    for (int j = 0; j < 32; j++) gv[j] = stg[er * 132 + ec0 + j];
    __syncthreads();
    if (mat == 1) {
        #pragma unroll
        for (int m = 0; m < 4; m++)
            #pragma unroll
            for (int n = 0; n < 2; n++)
                wmma::store_matrix_sync(stg + (wm * 64 + m * 16) * 132 + wn * 32 + n * 16,
                                        c[m][n], 132, wmma::mem_row_major);
    }
    __syncthreads();
    {
        const size_t hrow = (size_t)e * 2048 + rb * 128 + er;
        __nv_bfloat16* hh = g_Hh + hrow * FF + (size_t)nb * 128 + ec0;
        __nv_bfloat16* hl = g_Hl + hrow * FF + (size_t)nb * 128 + ec0;
        unsigned short hv[32], lv[32];
        #pragma unroll
        for (int j = 0; j < 32; j++) {
            float g = gv[j];
            float u = stg[er * 132 + ec0 + j];
            float h = (g / (1.f + expf(-g))) * u;
            split1(h, hv[j], lv[j]);
        }
        #pragma unroll
        for (int q = 0; q < 4; q++) {
            *(uint4*)(hh + q * 8) = make_uint4(pk2(hv[q*8+0],hv[q*8+1]), pk2(hv[q*8+2],hv[q*8+3]),
                                               pk2(hv[q*8+4],hv[q*8+5]), pk2(hv[q*8+6],hv[q*8+7]));
            *(uint4*)(hl + q * 8) = make_uint4(pk2(lv[q*8+0],lv[q*8+1]), pk2(lv[q*8+2],lv[q*8+3]),
                                               pk2(lv[q*8+4],lv[q*8+5]), pk2(lv[q*8+6],lv[q*8+7]));
        }
    }
    #undef GU_LOAD
}

// ================= GEMM2: down-proj (bf16x3 HMMA) + gated atomic accumulate =================
// BM=256, BN=128, BK=32, 512 threads = 16 warps: wm = warp>>2 (4), wn = warp&3 (4); warp 64x32.
__global__ __launch_bounds__(512, 1) void gemm_down(float* __restrict__ out)
{
    const int e  = blockIdx.x >> 3;
    const int rb = blockIdx.x & 7;
    const int ne = g_cnt[e];
    if (rb * 256 >= ne) return;
    const int nb = blockIdx.y;

    extern __shared__ char smem[];
    const uint32_t sb = smem_u32(smem);
    const int tid  = threadIdx.x;
    const int warp = tid >> 5;
    const int wm   = warp >> 2;
    const int wn   = warp & 3;

    // A loader: 256 rows x 4 chunks -> 1024 slots -> 2 per thread per plane
    const int arow = tid >> 2, achk = (tid & 3) * 8;
    const size_t hbase = ((size_t)e * 2048 + rb * 256);
    const __nv_bfloat16* sAh0 = g_Hh + (hbase + arow) * FF + achk;
    const __nv_bfloat16* sAl0 = g_Hl + (hbase + arow) * FF + achk;
    const __nv_bfloat16* sAh1 = sAh0 + (size_t)128 * FF;
    const __nv_bfloat16* sAl1 = sAl0 + (size_t)128 * FF;
    const uint32_t dA0 = sb + (uint32_t)arow * 80 + achk * 2;
    const uint32_t dA1 = dA0 + 128 * 80;

    // B loader: 32 rows x 16 chunks -> 512 slots
    const int brow = tid >> 4, bchk = (tid & 15) * 8;
    const size_t wb = (size_t)e * FF * DD + (size_t)brow * DD + (size_t)nb * 128 + bchk;
    const __nv_bfloat16* sBh = g_Wd_hi + wb;
    const __nv_bfloat16* sBl = g_Wd_lo + wb;
    const uint32_t dB = sb + 2 * DN_AB + (uint32_t)brow * 272 + bchk * 2;

    #define DN_LOAD(st, k) do { \
        uint32_t o = (uint32_t)(st) * DN_STG; size_t kf = (size_t)(k) * DD; \
        cpa16(dA0 + o,          sAh0 + (k)); \
        cpa16(dA0 + o + DN_AB,  sAl0 + (k)); \
        cpa16(dA1 + o,          sAh1 + (k)); \
        cpa16(dA1 + o + DN_AB,  sAl1 + (k)); \
        cpa16(dB + o,           sBh + kf); \
        cpa16(dB + o + DN_BB,   sBl + kf); \
    } while (0)

    FragC c[4][2];
    #pragma unroll
    for (int m = 0; m < 4; m++)
        #pragma unroll
        for (int n = 0; n < 2; n++) wmma::fill_fragment(c[m][n], 0.f);

    DN_LOAD(0, 0);  CPA_COMMIT();
    DN_LOAD(1, 32); CPA_COMMIT();

    const int NS = FF / 32;   // 256
    #pragma unroll 1
    for (int s = 0; s < NS; s++) {
        if (s + 1 < NS) CPA_WAIT1(); else CPA_WAIT0();
        __syncthreads();

        const char* base = smem + (s & 1) * DN_STG;
        const __nv_bfloat16* Ah = (const __nv_bfloat16*)(base);
        const __nv_bfloat16* Al = (const __nv_bfloat16*)(base + DN_AB);
        const __nv_bfloat16* Bh = (const __nv_bfloat16*)(base + 2 * DN_AB);
        const __nv_bfloat16* Bl = (const __nv_bfloat16*)(base + 2 * DN_AB + DN_BB);

        #pragma unroll
        for (int ks = 0; ks < 32; ks += 16) {
            FragA ah[4], al[4];
            #pragma unroll
            for (int m = 0; m < 4; m++) {
                wmma::load_matrix_sync(ah[m], Ah + (wm * 64 + m * 16) * 40 + ks, 40);
                wmma::load_matrix_sync(al[m], Al + (wm * 64 + m * 16) * 40 + ks, 40);
            }
            #pragma unroll
            for (int n = 0; n < 2; n++) {
                const int nc = wn * 32 + n * 16;
                FragB bh, bl;
                wmma::load_matrix_sync(bh, Bh + ks * 136 + nc, 136);
                wmma::load_matrix_sync(bl, Bl + ks * 136 + nc, 136);
                #pragma unroll
                for (int m = 0; m < 4; m++) {
                    wmma::mma_sync(c[m][n], ah[m], bh, c[m][n]);
                    wmma::mma_sync(c[m][n], ah[m], bl, c[m][n]);
                    wmma::mma_sync(c[m][n], al[m], bh, c[m][n]);
                }
            }
        }
        __syncthreads();
        if (s + 2 < NS) { DN_LOAD(s & 1, (s + 2) * 32); CPA_COMMIT(); }
    }

    // epilogue: two halves of 128 rows via fp32 stage [128][132]; gated atomic adds
    float* stg = (float*)smem;
    const int er = tid >> 2, ec0 = (tid & 3) * 32;

    #pragma unroll
    for (int half = 0; half < 2; half++) {
        if ((wm >> 1) == half) {
            const int wmh = wm & 1;
            #pragma unroll
            for (int m = 0; m < 4; m++)
                #pragma unroll
                for (int n = 0; n < 2; n++)
                    wmma::store_matrix_sync(stg + (wmh * 64 + m * 16) * 132 + wn * 32 + n * 16,
                                            c[m][n], 132, wmma::mem_row_major);
        }
        __syncthreads();
        {
            const int grow = rb * 256 + half * 128 + er;
            if (grow < ne) {
                const int   tok = g_tok[e][grow];
                const float gv  = g_gate[e][grow];
                float* orow = out + (size_t)tok * DD + (size_t)nb * 128 + ec0;
                #pragma unroll
                for (int j = 0; j < 32; j++)
                    atomicAdd(&orow[j], gv * stg[er * 132 + ec0 + j]);
            }
        }
        __syncthreads();
    }
    #undef DN_LOAD
}

// ---------------- launch ----------------
extern "C" void kernel_launch(void* const* d_in, const int* in_sizes, int n_in,
                              void* d_out, int out_size) {
    const float* x  = (const float*)d_in[0];
    const float* Wr = (const float*)d_in[1];
    const float* Wg = (const float*)d_in[2];
    const float* Wu = (const float*)d_in[3];
    const float* Wd = (const float*)d_in[4];
    float* out = (float*)d_out;

    static int attr_done = 0;
    if (!attr_done) {
        cudaFuncSetAttribute(gemm_gateup, cudaFuncAttributeMaxDynamicSharedMemorySize, GU_SMEM);
        cudaFuncSetAttribute(gemm_down,   cudaFuncAttributeMaxDynamicSharedMemorySize, DN_SMEM);
        attr_done = 1;
    }

    const int n_out = NT * DD;
    init_kernel<<<(n_out + 255) / 256, 256>>>(out, n_out);

    // pre-split weights + x into bf16 hi/lo planes
    {
        __nv_bfloat16 *wg_h, *wg_l, *wu_h, *wu_l, *wd_h, *wd_l, *x_h, *x_l;
        cudaGetSymbolAddress((void**)&wg_h, g_Wg_hi); cudaGetSymbolAddress((void**)&wg_l, g_Wg_lo);
        cudaGetSymbolAddress((void**)&wu_h, g_Wu_hi); cudaGetSymbolAddress((void**)&wu_l, g_Wu_lo);
        cudaGetSymbolAddress((void**)&wd_h, g_Wd_hi); cudaGetSymbolAddress((void**)&wd_l, g_Wd_lo);
        cudaGetSymbolAddress((void**)&x_h,  g_x_hi);  cudaGetSymbolAddress((void**)&x_l,  g_x_lo);
        size_t w4 = WSZ / 4;
        split_kernel<<<(unsigned)((w4 + 255) / 256), 256>>>(Wg, wg_h, wg_l, w4);
        split_kernel<<<(unsigned)((w4 + 255) / 256), 256>>>(Wu, wu_h, wu_l, w4);
        split_kernel<<<(unsigned)((w4 + 255) / 256), 256>>>(Wd, wd_h, wd_l, w4);
        size_t x4 = (size_t)NT * DD / 4;
        split_kernel<<<(unsigned)((x4 + 255) / 256), 256>>>(x, x_h, x_l, x4);
    }

    router_kernel<<<(NT * 32 + 127) / 128, 128>>>(x, Wr);

    // all experts in one launch each; blockIdx.x = (expert<<k)|rowslot (fast-varying)
    gemm_gateup<<<dim3(EE * 16, FF / 128), 512, GU_SMEM>>>();
    gemm_down  <<<dim3(EE * 8,  DD / 128), 512, DN_SMEM>>>(out);
}